// round 10
// baseline (speedup 1.0000x reference)
#include <cuda_runtime.h>

// MultiIndexSelect: out[to_i[j]] = mat_i[from_i[j]], 3 segments of L rows,
// D=64 fp32 (256B/row). Two-pass scheme:
//
//   Pass 1: invert the scatter. pairs[to_i[j]] = {from_i[j], seg}.
//           9.6MB scratch, fits in L2, persists to pass 2 (L2 not flushed
//           between launches; only L1 is).
//   Pass 2: walk OUTPUT rows in order. Pair read is sequential (L2 hit),
//           gather stays random (compulsory), but the 307MB write side
//           becomes perfectly sequential streaming instead of a random
//           256B scatter -> much better HBM row-buffer efficiency.
//
// U=4 output rows per thread (strided slices) for MLP on the gather phase.

#define D4 16   // D=64 floats = 16 float4
#define U  4
#define PAIR_CAP 1300000   // > 3*L = 1.2M for this problem

__device__ int2 g_pairs[PAIR_CAP];

// ---------------- Pass 1: build inverse map ----------------
__global__ void __launch_bounds__(256)
mis_invert_kernel(const int* __restrict__ f0, const int* __restrict__ f1,
                  const int* __restrict__ f2, const int* __restrict__ t0,
                  const int* __restrict__ t1, const int* __restrict__ t2,
                  int L)
{
    int j = blockIdx.x * blockDim.x + threadIdx.x;
    if (j >= L) return;
    int a0 = __ldg(f0 + j), b0 = __ldg(t0 + j);
    int a1 = __ldg(f1 + j), b1 = __ldg(t1 + j);
    int a2 = __ldg(f2 + j), b2 = __ldg(t2 + j);
    g_pairs[b0] = make_int2(a0, 0);
    g_pairs[b1] = make_int2(a1, 1);
    g_pairs[b2] = make_int2(a2, 2);
}

// ---------------- Pass 2: stream output, random gather ----------------
__global__ void __launch_bounds__(256)
mis_stream_kernel(const float4* __restrict__ m0,
                  const float4* __restrict__ m1,
                  const float4* __restrict__ m2,
                  float4*       __restrict__ out,
                  int totalRows, int rowStride)
{
    const int tid  = blockIdx.x * blockDim.x + threadIdx.x;
    const int q    = tid & (D4 - 1);
    const int row0 = tid >> 4;

    const float4* srcp[U];
    bool act[U];
    int  rows[U];

    // Phase 1: sequential pair reads (L2-resident from pass 1), resolve
    // source addresses for all U rows.
    #pragma unroll
    for (int k = 0; k < U; k++) {
        const int row = row0 + k * rowStride;
        rows[k] = row;
        act[k]  = (row < totalRows);
        const int2 pr = act[k] ? g_pairs[row] : make_int2(0, 0);
        const float4* m = (pr.y == 0) ? m0 : (pr.y == 1) ? m1 : m2;
        srcp[k] = m + (size_t)pr.x * D4 + q;
    }

    // Phase 2: U independent random gathers in flight.
    float4 v[U];
    #pragma unroll
    for (int k = 0; k < U; k++) {
        if (act[k]) v[k] = __ldg(srcp[k]);
    }

    // Phase 3: perfectly sequential streaming writes (row-ordered).
    #pragma unroll
    for (int k = 0; k < U; k++) {
        if (act[k]) out[(size_t)rows[k] * D4 + q] = v[k];
    }
}

// ---------------- Fallback (single pass) if 3L exceeds scratch ----------------
__global__ void __launch_bounds__(256)
mis_generic_kernel(const float4* __restrict__ m0,
                   const float4* __restrict__ m1,
                   const float4* __restrict__ m2,
                   const int*    __restrict__ f0,
                   const int*    __restrict__ f1,
                   const int*    __restrict__ f2,
                   const int*    __restrict__ t0,
                   const int*    __restrict__ t1,
                   const int*    __restrict__ t2,
                   float4*       __restrict__ out,
                   int L)
{
    int tid = blockIdx.x * blockDim.x + threadIdx.x;
    int row = tid >> 4;
    int q   = tid & (D4 - 1);
    if (row >= 3 * L) return;
    const float4* m; const int* f; const int* t; int r;
    if (row < L)          { m = m0; f = f0; t = t0; r = row;         }
    else if (row < 2 * L) { m = m1; f = f1; t = t1; r = row - L;     }
    else                  { m = m2; f = f2; t = t2; r = row - 2 * L; }
    int src = __ldg(f + r);
    int dst = __ldg(t + r);
    out[(size_t)dst * D4 + q] = __ldg(m + (size_t)src * D4 + q);
}

extern "C" void kernel_launch(void* const* d_in, const int* in_sizes, int n_in,
                              void* d_out, int out_size)
{
    const float4* m0 = (const float4*)d_in[0];
    const float4* m1 = (const float4*)d_in[1];
    const float4* m2 = (const float4*)d_in[2];
    const int*    f0 = (const int*)d_in[3];
    const int*    f1 = (const int*)d_in[4];
    const int*    f2 = (const int*)d_in[5];
    const int*    t0 = (const int*)d_in[6];
    const int*    t1 = (const int*)d_in[7];
    const int*    t2 = (const int*)d_in[8];
    float4* out = (float4*)d_out;

    const int L         = in_sizes[3];
    const int totalRows = 3 * L;
    const int block     = 256;

    if (totalRows <= PAIR_CAP) {
        // Pass 1: invert scatter into g_pairs (L2-resident, 9.6MB).
        const int grid1 = (L + block - 1) / block;
        mis_invert_kernel<<<grid1, block>>>(f0, f1, f2, t0, t1, t2, L);

        // Pass 2: sequential output streaming, random gather, MLP=U.
        const int rowStride = (totalRows + U - 1) / U;
        const long long threads = (long long)rowStride * D4;
        const int grid2 = (int)((threads + block - 1) / block);
        mis_stream_kernel<<<grid2, block>>>(m0, m1, m2, out,
                                            totalRows, rowStride);
    } else {
        const long long threads = (long long)totalRows * D4;
        const int grid = (int)((threads + block - 1) / block);
        mis_generic_kernel<<<grid, block>>>(m0, m1, m2, f0, f1, f2,
                                            t0, t1, t2, out, L);
    }
}

// round 13
// speedup vs baseline: 1.0737x; 1.0737x over previous
#include <cuda_runtime.h>

// out[to_i[j]] = mat_i[from_i[j]], 3 segments of L rows, D=64 fp32 (256B/row).
// Best-known structure (R5): 16 threads per row, U=6 rows/thread with
// compile-time segment mapping (rows {r0, r0+L/2} of each segment):
// 6 from-index loads, 6 independent LDG.128 gathers (MLP=6), 6 to-index
// loads, 6 STG.128 scatters. Traffic is at the compulsory minimum (~528MB);
// DRAM efficiency (~79% of 8TB/s on random 256B rows) is the binder.
// R10: block=512, from-indices loaded ahead of to-indices so gathers issue
// one memory-op earlier on the per-thread critical path.

#define D4 16   // D=64 floats = 16 float4

__global__ void __launch_bounds__(512)
mis_u6_kernel(const float4* __restrict__ m0,
              const float4* __restrict__ m1,
              const float4* __restrict__ m2,
              const int*    __restrict__ f0,
              const int*    __restrict__ f1,
              const int*    __restrict__ f2,
              const int*    __restrict__ t0,
              const int*    __restrict__ t1,
              const int*    __restrict__ t2,
              float4*       __restrict__ out,
              int halfL)
{
    const int tid = blockIdx.x * blockDim.x + threadIdx.x;
    const int q   = tid & (D4 - 1);
    const int r0  = tid >> 4;                 // [0, halfL)
    if (r0 >= halfL) return;
    const int r1  = r0 + halfL;

    // Phase 1a: source indices first — gathers can issue as soon as these land.
    const int s0 = __ldg(f0 + r0);
    const int s1 = __ldg(f0 + r1);
    const int s2 = __ldg(f1 + r0);
    const int s3 = __ldg(f1 + r1);
    const int s4 = __ldg(f2 + r0);
    const int s5 = __ldg(f2 + r1);

    // Phase 2: 6 independent 16B gathers in flight (MLP=6).
    float4 v0 = __ldg(m0 + (size_t)s0 * D4 + q);
    float4 v1 = __ldg(m0 + (size_t)s1 * D4 + q);
    float4 v2 = __ldg(m1 + (size_t)s2 * D4 + q);
    float4 v3 = __ldg(m1 + (size_t)s3 * D4 + q);
    float4 v4 = __ldg(m2 + (size_t)s4 * D4 + q);
    float4 v5 = __ldg(m2 + (size_t)s5 * D4 + q);

    // Phase 1b: destination indices — overlap with gather latency.
    const int d0 = __ldg(t0 + r0);
    const int d1 = __ldg(t0 + r1);
    const int d2 = __ldg(t1 + r0);
    const int d3 = __ldg(t1 + r1);
    const int d4 = __ldg(t2 + r0);
    const int d5 = __ldg(t2 + r1);

    // Phase 3: scatters (full-line coalesced per 16-thread group).
    out[(size_t)d0 * D4 + q] = v0;
    out[(size_t)d1 * D4 + q] = v1;
    out[(size_t)d2 * D4 + q] = v2;
    out[(size_t)d3 * D4 + q] = v3;
    out[(size_t)d4 * D4 + q] = v4;
    out[(size_t)d5 * D4 + q] = v5;
}

// Generic fallback (used only if L is odd): one thread per row-float4.
__global__ void __launch_bounds__(512)
mis_generic_kernel(const float4* __restrict__ m0,
                   const float4* __restrict__ m1,
                   const float4* __restrict__ m2,
                   const int*    __restrict__ f0,
                   const int*    __restrict__ f1,
                   const int*    __restrict__ f2,
                   const int*    __restrict__ t0,
                   const int*    __restrict__ t1,
                   const int*    __restrict__ t2,
                   float4*       __restrict__ out,
                   int L)
{
    int tid = blockIdx.x * blockDim.x + threadIdx.x;
    int row = tid >> 4;
    int q   = tid & (D4 - 1);
    if (row >= 3 * L) return;
    const float4* m; const int* f; const int* t; int r;
    if (row < L)          { m = m0; f = f0; t = t0; r = row;         }
    else if (row < 2 * L) { m = m1; f = f1; t = t1; r = row - L;     }
    else                  { m = m2; f = f2; t = t2; r = row - 2 * L; }
    int src = __ldg(f + r);
    int dst = __ldg(t + r);
    out[(size_t)dst * D4 + q] = __ldg(m + (size_t)src * D4 + q);
}

extern "C" void kernel_launch(void* const* d_in, const int* in_sizes, int n_in,
                              void* d_out, int out_size)
{
    const float4* m0 = (const float4*)d_in[0];
    const float4* m1 = (const float4*)d_in[1];
    const float4* m2 = (const float4*)d_in[2];
    const int*    f0 = (const int*)d_in[3];
    const int*    f1 = (const int*)d_in[4];
    const int*    f2 = (const int*)d_in[5];
    const int*    t0 = (const int*)d_in[6];
    const int*    t1 = (const int*)d_in[7];
    const int*    t2 = (const int*)d_in[8];
    float4* out = (float4*)d_out;

    const int L     = in_sizes[3];     // length of from0
    const int block = 512;

    if ((L & 1) == 0) {
        const int halfL = L >> 1;
        const long long threads = (long long)halfL * D4;
        const int grid = (int)((threads + block - 1) / block);
        mis_u6_kernel<<<grid, block>>>(m0, m1, m2, f0, f1, f2,
                                       t0, t1, t2, out, halfL);
    } else {
        const long long threads = (long long)3 * L * D4;
        const int grid = (int)((threads + block - 1) / block);
        mis_generic_kernel<<<grid, block>>>(m0, m1, m2, f0, f1, f2,
                                            t0, t1, t2, out, L);
    }
}

// round 14
// speedup vs baseline: 1.0799x; 1.0058x over previous
#include <cuda_runtime.h>

// out[to_i[j]] = mat_i[from_i[j]], 3 segments of L rows, D=64 fp32 (256B/row).
// Final form: 16 threads per row, U=6 rows/thread, compile-time segment map
// (rows {r0, r0+L/2} of each segment), block=256 with exact-fit grid.
//   Phase 1a: 6 from-index loads (L1-cached; high hit rate, warp-broadcast)
//   Phase 2 : 6 independent LDG.128 gathers via __ldcg (L2-only — random rows
//             never hit L1, so don't pollute it)
//   Phase 1b: 6 to-index loads overlapped with gather latency
//   Phase 3 : 6 coalesced STG.128 scatters
// Measured: traffic = compulsory minimum (~528MB); binder is HBM efficiency
// on random 256B rows (~78% of 8TB/s). Latency fully covered at MLP=6/occ 84%.

#define D4 16   // D=64 floats = 16 float4

__device__ __forceinline__ float4 ldcg4(const float4* p) {
    float4 v;
    asm volatile("ld.global.cg.v4.f32 {%0, %1, %2, %3}, [%4];"
                 : "=f"(v.x), "=f"(v.y), "=f"(v.z), "=f"(v.w) : "l"(p));
    return v;
}

__global__ void __launch_bounds__(256)
mis_u6_kernel(const float4* __restrict__ m0,
              const float4* __restrict__ m1,
              const float4* __restrict__ m2,
              const int*    __restrict__ f0,
              const int*    __restrict__ f1,
              const int*    __restrict__ f2,
              const int*    __restrict__ t0,
              const int*    __restrict__ t1,
              const int*    __restrict__ t2,
              float4*       __restrict__ out,
              int halfL)
{
    const int tid = blockIdx.x * blockDim.x + threadIdx.x;
    const int q   = tid & (D4 - 1);
    const int r0  = tid >> 4;                 // [0, halfL)
    if (r0 >= halfL) return;
    const int r1  = r0 + halfL;

    // Phase 1a: source indices (L1-friendly, warp-broadcast).
    const int s0 = __ldg(f0 + r0);
    const int s1 = __ldg(f0 + r1);
    const int s2 = __ldg(f1 + r0);
    const int s3 = __ldg(f1 + r1);
    const int s4 = __ldg(f2 + r0);
    const int s5 = __ldg(f2 + r1);

    // Phase 2: 6 independent 16B gathers in flight, L2-only caching.
    float4 v0 = ldcg4(m0 + (size_t)s0 * D4 + q);
    float4 v1 = ldcg4(m0 + (size_t)s1 * D4 + q);
    float4 v2 = ldcg4(m1 + (size_t)s2 * D4 + q);
    float4 v3 = ldcg4(m1 + (size_t)s3 * D4 + q);
    float4 v4 = ldcg4(m2 + (size_t)s4 * D4 + q);
    float4 v5 = ldcg4(m2 + (size_t)s5 * D4 + q);

    // Phase 1b: destination indices, overlapped with gather latency.
    const int d0 = __ldg(t0 + r0);
    const int d1 = __ldg(t0 + r1);
    const int d2 = __ldg(t1 + r0);
    const int d3 = __ldg(t1 + r1);
    const int d4 = __ldg(t2 + r0);
    const int d5 = __ldg(t2 + r1);

    // Phase 3: scatters (full-line coalesced per 16-thread group).
    out[(size_t)d0 * D4 + q] = v0;
    out[(size_t)d1 * D4 + q] = v1;
    out[(size_t)d2 * D4 + q] = v2;
    out[(size_t)d3 * D4 + q] = v3;
    out[(size_t)d4 * D4 + q] = v4;
    out[(size_t)d5 * D4 + q] = v5;
}

// Generic fallback (used only if L is odd): one thread per row-float4.
__global__ void __launch_bounds__(256)
mis_generic_kernel(const float4* __restrict__ m0,
                   const float4* __restrict__ m1,
                   const float4* __restrict__ m2,
                   const int*    __restrict__ f0,
                   const int*    __restrict__ f1,
                   const int*    __restrict__ f2,
                   const int*    __restrict__ t0,
                   const int*    __restrict__ t1,
                   const int*    __restrict__ t2,
                   float4*       __restrict__ out,
                   int L)
{
    int tid = blockIdx.x * blockDim.x + threadIdx.x;
    int row = tid >> 4;
    int q   = tid & (D4 - 1);
    if (row >= 3 * L) return;
    const float4* m; const int* f; const int* t; int r;
    if (row < L)          { m = m0; f = f0; t = t0; r = row;         }
    else if (row < 2 * L) { m = m1; f = f1; t = t1; r = row - L;     }
    else                  { m = m2; f = f2; t = t2; r = row - 2 * L; }
    int src = __ldg(f + r);
    int dst = __ldg(t + r);
    out[(size_t)dst * D4 + q] = __ldg(m + (size_t)src * D4 + q);
}

extern "C" void kernel_launch(void* const* d_in, const int* in_sizes, int n_in,
                              void* d_out, int out_size)
{
    const float4* m0 = (const float4*)d_in[0];
    const float4* m1 = (const float4*)d_in[1];
    const float4* m2 = (const float4*)d_in[2];
    const int*    f0 = (const int*)d_in[3];
    const int*    f1 = (const int*)d_in[4];
    const int*    f2 = (const int*)d_in[5];
    const int*    t0 = (const int*)d_in[6];
    const int*    t1 = (const int*)d_in[7];
    const int*    t2 = (const int*)d_in[8];
    float4* out = (float4*)d_out;

    const int L     = in_sizes[3];     // length of from0
    const int block = 256;

    if ((L & 1) == 0) {
        const int halfL = L >> 1;
        const long long threads = (long long)halfL * D4;
        const int grid = (int)((threads + block - 1) / block);
        mis_u6_kernel<<<grid, block>>>(m0, m1, m2, f0, f1, f2,
                                       t0, t1, t2, out, halfL);
    } else {
        const long long threads = (long long)3 * L * D4;
        const int grid = (int)((threads + block - 1) / block);
        mis_generic_kernel<<<grid, block>>>(m0, m1, m2, f0, f1, f2,
                                            t0, t1, t2, out, L);
    }
}